// round 14
// baseline (speedup 1.0000x reference)
#include <cuda_runtime.h>
#include <cuda_fp16.h>

#define BATCH 4
#define SEQ   8192
#define DIM   512
#define M_TOTAL (BATCH*SEQ)   // 32768

#define NCHUNK 128
#define CHUNK  64

#define TILE_M 128
#define TILE_N 64
#define BK     32
#define NSTG   (DIM/BK)       // 16
#define STAGES 4

#define A_PITCH_B 80                     // bytes per A row (32 halfs + 8 pad)
#define A_BYTES   (TILE_M*A_PITCH_B)     // 10240
#define B_PITCH_B 144                    // bytes per B k-row (64 halfs + 8 pad)
#define B_GATE    (BK*B_PITCH_B)         // 4608
#define B_BYTES   (3*B_GATE)             // 13824
#define STG_BYTES (A_BYTES+B_BYTES)      // 24064
#define DYN_SMEM  (1024 + STAGES*STG_BYTES)

// ---------------- scratch ---------------------------------------------------
__device__ __half  g_x16[(size_t)M_TOTAL*DIM];   // x in fp16, 32MB
__device__ __half  g_w16[3*DIM*DIM];             // W fp16, [w][k][n], 1.5MB
__device__ __half2 g_fv[(size_t)M_TOTAL*DIM];    // (f,v) packed, 64MB
__device__ float   g_P[NCHUNK*BATCH*DIM];
__device__ float   g_V[NCHUNK*BATCH*DIM];
__device__ float   g_hin[NCHUNK*BATCH*DIM];

__device__ __forceinline__ float sigmoidf_(float x) { return 1.0f / (1.0f + __expf(-x)); }
__device__ __forceinline__ unsigned smem_u32(const void* p) {
    unsigned a;
    asm("{ .reg .u64 t; cvta.to.shared.u64 t, %1; cvt.u32.u64 %0, t; }" : "=r"(a) : "l"(p));
    return a;
}
__device__ __forceinline__ void cpasync16(unsigned dst, const void* src) {
    asm volatile("cp.async.cg.shared.global [%0], [%1], 16;" :: "r"(dst), "l"(src));
}
__device__ __forceinline__ void ldsm4(unsigned* r, unsigned addr) {
    asm volatile("ldmatrix.sync.aligned.m8n8.x4.shared.b16 {%0,%1,%2,%3}, [%4];"
                 : "=r"(r[0]), "=r"(r[1]), "=r"(r[2]), "=r"(r[3]) : "r"(addr));
}
__device__ __forceinline__ void ldsm4t(unsigned* r, unsigned addr) {
    asm volatile("ldmatrix.sync.aligned.m8n8.x4.trans.shared.b16 {%0,%1,%2,%3}, [%4];"
                 : "=r"(r[0]), "=r"(r[1]), "=r"(r[2]), "=r"(r[3]) : "r"(addr));
}
__device__ __forceinline__ void mma16816(float* c, const unsigned* a, unsigned b0, unsigned b1) {
    asm volatile("mma.sync.aligned.m16n8k16.row.col.f32.f16.f16.f32 "
                 "{%0,%1,%2,%3}, {%4,%5,%6,%7}, {%8,%9}, {%0,%1,%2,%3};"
                 : "+f"(c[0]), "+f"(c[1]), "+f"(c[2]), "+f"(c[3])
                 : "r"(a[0]), "r"(a[1]), "r"(a[2]), "r"(a[3]), "r"(b0), "r"(b1));
}

// ---------------- prep: x -> fp16 AND W -> fp16, 8 elems/thread -------------
#define WBLKS (3*DIM*DIM/2048)          // 384
#define XBLKS (M_TOTAL*DIM/2048)        // 8192

__global__ __launch_bounds__(256) void prep(
    const float* __restrict__ x,
    const float* __restrict__ Wf, const float* __restrict__ Wi,
    const float* __restrict__ Wh)
{
    if (blockIdx.x < WBLKS) {
        size_t j = ((size_t)blockIdx.x * 256 + threadIdx.x) * 8;
        int w = (int)(j >> 18);
        size_t off = j & (DIM*DIM - 1);
        const float* W = (w == 0) ? Wf : (w == 1) ? Wi : Wh;
        float4 t0 = *(const float4*)(W + off);
        float4 t1 = *(const float4*)(W + off + 4);
        __half2 h[4] = { __floats2half2_rn(t0.x, t0.y), __floats2half2_rn(t0.z, t0.w),
                         __floats2half2_rn(t1.x, t1.y), __floats2half2_rn(t1.z, t1.w) };
        *(float4*)(g_w16 + (size_t)w * DIM * DIM + off) = *(float4*)h;
    } else {
        size_t i = ((size_t)(blockIdx.x - WBLKS) * 256 + threadIdx.x) * 8;
        float4 t0 = *(const float4*)(x + i);
        float4 t1 = *(const float4*)(x + i + 4);
        __half2 h[4] = { __floats2half2_rn(t0.x, t0.y), __floats2half2_rn(t0.z, t0.w),
                         __floats2half2_rn(t1.x, t1.y), __floats2half2_rn(t1.z, t1.w) };
        *(float4*)(g_x16 + i) = *(float4*)h;
    }
}

// ---------------- fp16 mma.sync GEMM + activations + fused chunk reduce -----
// (R11 verbatim)
__global__ __launch_bounds__(256) void gemm_act(
    const float* __restrict__ bfp, const float* __restrict__ bip,
    const float* __restrict__ bhp)
{
    extern __shared__ char dsm[];
    __shared__ float s_bias[3*TILE_N];

    const int tid  = threadIdx.x;
    const int wid  = tid >> 5;
    const int lane = tid & 31;
    const int wm   = wid >> 1;   // 0..3
    const int wn   = wid & 1;    // 0..1
    const int n0   = blockIdx.x * TILE_N;
    const int m0   = blockIdx.y * TILE_M;

    unsigned raw = smem_u32(dsm);
    unsigned sma = (raw + 1023u) & ~1023u;

    if (tid < 3*TILE_N) {
        int w = tid >> 6, c = tid & 63;
        const float* b = (w == 0) ? bfp : (w == 1) ? bip : bhp;
        s_bias[tid] = b[n0 + c];
    }

    float acc[3][2][4][4];
    #pragma unroll
    for (int g = 0; g < 3; g++)
        #pragma unroll
        for (int mi = 0; mi < 2; mi++)
            #pragma unroll
            for (int ni = 0; ni < 4; ni++)
                #pragma unroll
                for (int r = 0; r < 4; r++)
                    acc[g][mi][ni][r] = 0.0f;

    auto fill = [&](int buf, int k0e) {
        unsigned sb = sma + buf * STG_BYTES;
        #pragma unroll
        for (int i = 0; i < 2; i++) {          // A: 512 chunks
            int c = tid + 256 * i;
            int r = c >> 2, q = c & 3;
            cpasync16(sb + (unsigned)(r * A_PITCH_B + q * 16),
                      g_x16 + (size_t)(m0 + r) * DIM + k0e + q * 8);
        }
        #pragma unroll
        for (int i = 0; i < 3; i++) {          // B: 768 chunks
            int c = tid + 256 * i;
            int g = c >> 8, rq = c & 255;
            int k = rq >> 3, q = rq & 7;
            cpasync16(sb + (unsigned)(A_BYTES + g * B_GATE + k * B_PITCH_B + q * 16),
                      g_w16 + (size_t)g * DIM * DIM + (size_t)(k0e + k) * DIM + n0 + q * 8);
        }
        asm volatile("cp.async.commit_group;");
    };

    #pragma unroll
    for (int s = 0; s < STAGES - 1; s++) fill(s, s * BK);

    const int l15 = lane & 15;
    const int l16 = lane >> 4;

    for (int i = 0; i < NSTG; i++) {
        asm volatile("cp.async.wait_group %0;" :: "n"(STAGES - 2));
        __syncthreads();
        int j = i + STAGES - 1;
        if (j < NSTG) fill(j & (STAGES - 1), j * BK);
        else          asm volatile("cp.async.commit_group;");

        unsigned sb = sma + (i & (STAGES - 1)) * STG_BYTES;

        #pragma unroll
        for (int kh = 0; kh < 2; kh++) {
            int kk = kh * 16;
            unsigned a[2][4];
            #pragma unroll
            for (int mi = 0; mi < 2; mi++)
                ldsm4(a[mi], sb + (unsigned)((wm * 32 + mi * 16 + l15) * A_PITCH_B
                                              + (kk + l16 * 8) * 2));
            #pragma unroll
            for (int g = 0; g < 3; g++) {
                unsigned b[2][4];
                #pragma unroll
                for (int nh = 0; nh < 2; nh++)
                    ldsm4t(b[nh], sb + (unsigned)(A_BYTES + g * B_GATE
                                                  + (kk + l15) * B_PITCH_B
                                                  + (wn * 32 + nh * 16 + l16 * 8) * 2));
                #pragma unroll
                for (int ni = 0; ni < 4; ni++) {
                    unsigned b0 = b[ni >> 1][(ni & 1) * 2];
                    unsigned b1 = b[ni >> 1][(ni & 1) * 2 + 1];
                    #pragma unroll
                    for (int mi = 0; mi < 2; mi++)
                        mma16816(acc[g][mi][ni], a[mi], b0, b1);
                }
            }
        }
    }

    // ---- epilogue: activations -> smem staging (half2 f,v) ----
    __half2* sfv = (__half2*)(dsm + (sma - raw));
    const int PITCH = 65;   // half2 units per m-row

    #pragma unroll
    for (int mi = 0; mi < 2; mi++) {
        #pragma unroll
        for (int ni = 0; ni < 4; ni++) {
            int lm = wm * 32 + mi * 16 + (lane >> 2);
            int ln = wn * 32 + ni * 8 + 2 * (lane & 3);
            #pragma unroll
            for (int half = 0; half < 2; half++) {
                int m = lm + half * 8;
                #pragma unroll
                for (int e = 0; e < 2; e++) {
                    int c = ln + e;
                    float yf = acc[0][mi][ni][half * 2 + e] + s_bias[c];
                    float yi = acc[1][mi][ni][half * 2 + e] + s_bias[TILE_N + c];
                    float yh = acc[2][mi][ni][half * 2 + e] + s_bias[2*TILE_N + c];
                    float f  = sigmoidf_(yf);
                    float gg = (yh >= 0.0f) ? (yh + 0.5f) : sigmoidf_(yh);
                    float v  = sigmoidf_(yi) * gg;
                    sfv[m * PITCH + c] = __floats2half2_rn(f, v);
                }
            }
        }
    }
    __syncthreads();

    // ---- fused reduction: two 64-step chunks per tile ----
    {
        int c = tid >> 2;
        int q = tid & 3;          // segment: rows q*32 .. q*32+31
        float P = 1.0f, V = 0.0f;
        #pragma unroll 8
        for (int s = 0; s < 32; s++) {
            float2 fv = __half22float2(sfv[(q * 32 + s) * PITCH + c]);
            V = fmaf(fv.x, V, fv.y);
            P *= fv.x;
        }
        float Po = __shfl_xor_sync(0xffffffff, P, 1);
        float Vo = __shfl_xor_sync(0xffffffff, V, 1);
        if ((q & 1) == 0) V = fmaf(Po, V, Vo);
        else              V = fmaf(P, Vo, V);
        P *= Po;
        if ((q & 1) == 0) {
            int bb = m0 / SEQ;
            int ck = (m0 % SEQ) / CHUNK + (q >> 1);
            size_t idx = (size_t)ck * (BATCH*DIM) + bb * DIM + n0 + c;
            g_P[idx] = P;
            g_V[idx] = V;
        }
    }

    // ---- store staging tile to global (coalesced) ----
    #pragma unroll 8
    for (int t = 0; t < 32; t++) {
        int idx = tid + 256 * t;
        int m = idx >> 6, c = idx & 63;
        g_fv[(size_t)(m0 + m) * DIM + n0 + c] = sfv[m * PITCH + c];
    }
}

// ---------------- carry scan over 128 chunks (2 batches of reg-preload) -----
__global__ __launch_bounds__(512) void carry_scan(const float* __restrict__ pre_h)
{
    int ch = blockIdx.x * 512 + threadIdx.x;   // 0..2047
    float pv = pre_h[ch];
    float h = (pv >= 0.0f) ? (pv + 0.5f) : sigmoidf_(pv);
    #pragma unroll
    for (int half = 0; half < 2; half++) {
        float P[64], V[64];
        #pragma unroll
        for (int c = 0; c < 64; c++)
            P[c] = g_P[(size_t)(half * 64 + c) * (BATCH*DIM) + ch];
        #pragma unroll
        for (int c = 0; c < 64; c++)
            V[c] = g_V[(size_t)(half * 64 + c) * (BATCH*DIM) + ch];
        #pragma unroll
        for (int c = 0; c < 64; c++) {
            g_hin[(size_t)(half * 64 + c) * (BATCH*DIM) + ch] = h;
            h = fmaf(P[c], h, V[c]);
        }
    }
}

// ---------------- apply: 1024 blocks (~7/SM), CHUNK=64, streaming out -------
__global__ __launch_bounds__(256) void chunk_apply(float* __restrict__ out)
{
    int ck = blockIdx.x;
    int b  = blockIdx.y;
    int n  = blockIdx.z * 256 + threadIdx.x;
    float h = g_hin[(size_t)ck * (BATCH*DIM) + b * DIM + n];
    size_t base = ((size_t)(b * SEQ + ck * CHUNK)) * DIM + n;
    #pragma unroll 8
    for (int t = 0; t < CHUNK; t++) {
        float2 fv = __half22float2(g_fv[base + (size_t)t * DIM]);
        h = fmaf(fv.x, h, fv.y);
        __stcs(out + base + (size_t)t * DIM, h);   // out: write-once, evict-first
    }
}

// ---------------- launch ----------------------------------------------------
extern "C" void kernel_launch(void* const* d_in, const int* in_sizes, int n_in,
                              void* d_out, int out_size)
{
    const float* x     = (const float*)d_in[0];
    const float* pre_h = (const float*)d_in[1];
    const float* Wf    = (const float*)d_in[2];
    const float* bf    = (const float*)d_in[3];
    const float* Wi    = (const float*)d_in[4];
    const float* bi    = (const float*)d_in[5];
    const float* Wh    = (const float*)d_in[6];
    const float* bh    = (const float*)d_in[7];
    float* out = (float*)d_out;

    cudaFuncSetAttribute(gemm_act, cudaFuncAttributeMaxDynamicSharedMemorySize, DYN_SMEM);

    prep<<<WBLKS + XBLKS, 256>>>(x, Wf, Wi, Wh);
    gemm_act<<<dim3(DIM / TILE_N, M_TOTAL / TILE_M), 256, DYN_SMEM>>>(bf, bi, bh);
    carry_scan<<<4, 512>>>(pre_h);
    chunk_apply<<<dim3(NCHUNK, BATCH, 2), 256>>>(out);
}

// round 15
// speedup vs baseline: 1.0762x; 1.0762x over previous
#include <cuda_runtime.h>
#include <cuda_fp16.h>

#define BATCH 4
#define SEQ   8192
#define DIM   512
#define M_TOTAL (BATCH*SEQ)   // 32768

#define NCHUNK 128
#define CHUNK  64

#define TILE_M 128
#define TILE_N 64
#define BK     32
#define NSTG   (DIM/BK)       // 16
#define STAGES 4

#define A_PITCH_B 80                     // bytes per A row (32 halfs + 8 pad)
#define A_BYTES   (TILE_M*A_PITCH_B)     // 10240
#define B_PITCH_B 144                    // bytes per B k-row (64 halfs + 8 pad)
#define B_GATE    (BK*B_PITCH_B)         // 4608
#define B_BYTES   (3*B_GATE)             // 13824
#define STG_BYTES (A_BYTES+B_BYTES)      // 24064
#define DYN_SMEM  (1024 + STAGES*STG_BYTES)

// ---------------- scratch ---------------------------------------------------
__device__ __half  g_x16[(size_t)M_TOTAL*DIM];   // x in fp16, 32MB
__device__ __half  g_w16[3*DIM*DIM];             // W fp16, [w][k][n], 1.5MB
__device__ __half2 g_fv[(size_t)M_TOTAL*DIM];    // (f,v) packed, 64MB
__device__ float   g_P[NCHUNK*BATCH*DIM];
__device__ float   g_V[NCHUNK*BATCH*DIM];
__device__ float   g_hin[NCHUNK*BATCH*DIM];

__device__ __forceinline__ float sigmoidf_(float x) { return 1.0f / (1.0f + __expf(-x)); }
__device__ __forceinline__ unsigned smem_u32(const void* p) {
    unsigned a;
    asm("{ .reg .u64 t; cvta.to.shared.u64 t, %1; cvt.u32.u64 %0, t; }" : "=r"(a) : "l"(p));
    return a;
}
__device__ __forceinline__ void cpasync16(unsigned dst, const void* src) {
    asm volatile("cp.async.cg.shared.global [%0], [%1], 16;" :: "r"(dst), "l"(src));
}
__device__ __forceinline__ void ldsm4(unsigned* r, unsigned addr) {
    asm volatile("ldmatrix.sync.aligned.m8n8.x4.shared.b16 {%0,%1,%2,%3}, [%4];"
                 : "=r"(r[0]), "=r"(r[1]), "=r"(r[2]), "=r"(r[3]) : "r"(addr));
}
__device__ __forceinline__ void ldsm4t(unsigned* r, unsigned addr) {
    asm volatile("ldmatrix.sync.aligned.m8n8.x4.trans.shared.b16 {%0,%1,%2,%3}, [%4];"
                 : "=r"(r[0]), "=r"(r[1]), "=r"(r[2]), "=r"(r[3]) : "r"(addr));
}
__device__ __forceinline__ void mma16816(float* c, const unsigned* a, unsigned b0, unsigned b1) {
    asm volatile("mma.sync.aligned.m16n8k16.row.col.f32.f16.f16.f32 "
                 "{%0,%1,%2,%3}, {%4,%5,%6,%7}, {%8,%9}, {%0,%1,%2,%3};"
                 : "+f"(c[0]), "+f"(c[1]), "+f"(c[2]), "+f"(c[3])
                 : "r"(a[0]), "r"(a[1]), "r"(a[2]), "r"(a[3]), "r"(b0), "r"(b1));
}

// ---------------- prep: x -> fp16 AND W -> fp16 (merged; measured) ----------
#define WBLKS (3*DIM*DIM/1024)          // 768
#define XBLKS (M_TOTAL*DIM/1024)        // 16384

__global__ __launch_bounds__(256) void prep(
    const float* __restrict__ x,
    const float* __restrict__ Wf, const float* __restrict__ Wi,
    const float* __restrict__ Wh)
{
    if (blockIdx.x < WBLKS) {
        size_t j = ((size_t)blockIdx.x * 256 + threadIdx.x) * 4;
        int w = (int)(j >> 18);
        size_t off = j & (DIM*DIM - 1);
        const float* W = (w == 0) ? Wf : (w == 1) ? Wi : Wh;
        float4 t = *(const float4*)(W + off);
        *(__half2*)(g_w16 + (size_t)w * DIM * DIM + off)     = __floats2half2_rn(t.x, t.y);
        *(__half2*)(g_w16 + (size_t)w * DIM * DIM + off + 2) = __floats2half2_rn(t.z, t.w);
    } else {
        size_t i = ((size_t)(blockIdx.x - WBLKS) * 256 + threadIdx.x) * 4;
        float4 t = *(const float4*)(x + i);
        *(__half2*)(g_x16 + i)     = __floats2half2_rn(t.x, t.y);
        *(__half2*)(g_x16 + i + 2) = __floats2half2_rn(t.z, t.w);
    }
}

// ---------------- fp16 mma.sync GEMM + activations + fused chunk reduce -----
// (R11 verbatim)
__global__ __launch_bounds__(256) void gemm_act(
    const float* __restrict__ bfp, const float* __restrict__ bip,
    const float* __restrict__ bhp)
{
    extern __shared__ char dsm[];
    __shared__ float s_bias[3*TILE_N];

    const int tid  = threadIdx.x;
    const int wid  = tid >> 5;
    const int lane = tid & 31;
    const int wm   = wid >> 1;   // 0..3
    const int wn   = wid & 1;    // 0..1
    const int n0   = blockIdx.x * TILE_N;
    const int m0   = blockIdx.y * TILE_M;

    unsigned raw = smem_u32(dsm);
    unsigned sma = (raw + 1023u) & ~1023u;

    if (tid < 3*TILE_N) {
        int w = tid >> 6, c = tid & 63;
        const float* b = (w == 0) ? bfp : (w == 1) ? bip : bhp;
        s_bias[tid] = b[n0 + c];
    }

    float acc[3][2][4][4];
    #pragma unroll
    for (int g = 0; g < 3; g++)
        #pragma unroll
        for (int mi = 0; mi < 2; mi++)
            #pragma unroll
            for (int ni = 0; ni < 4; ni++)
                #pragma unroll
                for (int r = 0; r < 4; r++)
                    acc[g][mi][ni][r] = 0.0f;

    auto fill = [&](int buf, int k0e) {
        unsigned sb = sma + buf * STG_BYTES;
        #pragma unroll
        for (int i = 0; i < 2; i++) {          // A: 512 chunks
            int c = tid + 256 * i;
            int r = c >> 2, q = c & 3;
            cpasync16(sb + (unsigned)(r * A_PITCH_B + q * 16),
                      g_x16 + (size_t)(m0 + r) * DIM + k0e + q * 8);
        }
        #pragma unroll
        for (int i = 0; i < 3; i++) {          // B: 768 chunks
            int c = tid + 256 * i;
            int g = c >> 8, rq = c & 255;
            int k = rq >> 3, q = rq & 7;
            cpasync16(sb + (unsigned)(A_BYTES + g * B_GATE + k * B_PITCH_B + q * 16),
                      g_w16 + (size_t)g * DIM * DIM + (size_t)(k0e + k) * DIM + n0 + q * 8);
        }
        asm volatile("cp.async.commit_group;");
    };

    #pragma unroll
    for (int s = 0; s < STAGES - 1; s++) fill(s, s * BK);

    const int l15 = lane & 15;
    const int l16 = lane >> 4;

    for (int i = 0; i < NSTG; i++) {
        asm volatile("cp.async.wait_group %0;" :: "n"(STAGES - 2));
        __syncthreads();
        int j = i + STAGES - 1;
        if (j < NSTG) fill(j & (STAGES - 1), j * BK);
        else          asm volatile("cp.async.commit_group;");

        unsigned sb = sma + (i & (STAGES - 1)) * STG_BYTES;

        #pragma unroll
        for (int kh = 0; kh < 2; kh++) {
            int kk = kh * 16;
            unsigned a[2][4];
            #pragma unroll
            for (int mi = 0; mi < 2; mi++)
                ldsm4(a[mi], sb + (unsigned)((wm * 32 + mi * 16 + l15) * A_PITCH_B
                                              + (kk + l16 * 8) * 2));
            #pragma unroll
            for (int g = 0; g < 3; g++) {
                unsigned b[2][4];
                #pragma unroll
                for (int nh = 0; nh < 2; nh++)
                    ldsm4t(b[nh], sb + (unsigned)(A_BYTES + g * B_GATE
                                                  + (kk + l15) * B_PITCH_B
                                                  + (wn * 32 + nh * 16 + l16 * 8) * 2));
                #pragma unroll
                for (int ni = 0; ni < 4; ni++) {
                    unsigned b0 = b[ni >> 1][(ni & 1) * 2];
                    unsigned b1 = b[ni >> 1][(ni & 1) * 2 + 1];
                    #pragma unroll
                    for (int mi = 0; mi < 2; mi++)
                        mma16816(acc[g][mi][ni], a[mi], b0, b1);
                }
            }
        }
    }

    // ---- epilogue: activations -> smem staging (half2 f,v) ----
    __half2* sfv = (__half2*)(dsm + (sma - raw));
    const int PITCH = 65;   // half2 units per m-row

    #pragma unroll
    for (int mi = 0; mi < 2; mi++) {
        #pragma unroll
        for (int ni = 0; ni < 4; ni++) {
            int lm = wm * 32 + mi * 16 + (lane >> 2);
            int ln = wn * 32 + ni * 8 + 2 * (lane & 3);
            #pragma unroll
            for (int half = 0; half < 2; half++) {
                int m = lm + half * 8;
                #pragma unroll
                for (int e = 0; e < 2; e++) {
                    int c = ln + e;
                    float yf = acc[0][mi][ni][half * 2 + e] + s_bias[c];
                    float yi = acc[1][mi][ni][half * 2 + e] + s_bias[TILE_N + c];
                    float yh = acc[2][mi][ni][half * 2 + e] + s_bias[2*TILE_N + c];
                    float f  = sigmoidf_(yf);
                    float gg = (yh >= 0.0f) ? (yh + 0.5f) : sigmoidf_(yh);
                    float v  = sigmoidf_(yi) * gg;
                    sfv[m * PITCH + c] = __floats2half2_rn(f, v);
                }
            }
        }
    }
    __syncthreads();

    // ---- fused reduction: two 64-step chunks per tile ----
    {
        int c = tid >> 2;
        int q = tid & 3;          // segment: rows q*32 .. q*32+31
        float P = 1.0f, V = 0.0f;
        #pragma unroll 8
        for (int s = 0; s < 32; s++) {
            float2 fv = __half22float2(sfv[(q * 32 + s) * PITCH + c]);
            V = fmaf(fv.x, V, fv.y);
            P *= fv.x;
        }
        // combine segment pairs {0,1} and {2,3} -> one (P,V) per 64 steps
        float Po = __shfl_xor_sync(0xffffffff, P, 1);
        float Vo = __shfl_xor_sync(0xffffffff, V, 1);
        if ((q & 1) == 0) V = fmaf(Po, V, Vo);
        else              V = fmaf(P, Vo, V);
        P *= Po;
        if ((q & 1) == 0) {
            int bb = m0 / SEQ;
            int ck = (m0 % SEQ) / CHUNK + (q >> 1);
            size_t idx = (size_t)ck * (BATCH*DIM) + bb * DIM + n0 + c;
            g_P[idx] = P;
            g_V[idx] = V;
        }
    }

    // ---- store staging tile to global (coalesced) ----
    #pragma unroll 8
    for (int t = 0; t < 32; t++) {
        int idx = tid + 256 * t;
        int m = idx >> 6, c = idx & 63;
        g_fv[(size_t)(m0 + m) * DIM + n0 + c] = sfv[m * PITCH + c];
    }
}

// ---------------- carry scan over 128 chunks (2 batches of reg-preload) -----
__global__ void carry_scan(const float* __restrict__ pre_h)
{
    int ch = blockIdx.x * 256 + threadIdx.x;   // 0..2047
    float pv = pre_h[ch];
    float h = (pv >= 0.0f) ? (pv + 0.5f) : sigmoidf_(pv);
    #pragma unroll
    for (int half = 0; half < 2; half++) {
        float P[64], V[64];
        #pragma unroll
        for (int c = 0; c < 64; c++)
            P[c] = g_P[(size_t)(half * 64 + c) * (BATCH*DIM) + ch];
        #pragma unroll
        for (int c = 0; c < 64; c++)
            V[c] = g_V[(size_t)(half * 64 + c) * (BATCH*DIM) + ch];
        #pragma unroll
        for (int c = 0; c < 64; c++) {
            g_hin[(size_t)(half * 64 + c) * (BATCH*DIM) + ch] = h;
            h = fmaf(P[c], h, V[c]);
        }
    }
}

// ---------------- apply: 2048 blocks x 128thr (~14/SM), plain stores --------
__global__ __launch_bounds__(128) void chunk_apply(float* __restrict__ out)
{
    int ck = blockIdx.x;
    int b  = blockIdx.y;
    int n  = blockIdx.z * 128 + threadIdx.x;
    float h = g_hin[(size_t)ck * (BATCH*DIM) + b * DIM + n];
    size_t base = ((size_t)(b * SEQ + ck * CHUNK)) * DIM + n;
    #pragma unroll 8
    for (int t = 0; t < CHUNK; t++) {
        float2 fv = __half22float2(g_fv[base + (size_t)t * DIM]);
        h = fmaf(fv.x, h, fv.y);
        out[base + (size_t)t * DIM] = h;
    }
}

// ---------------- launch ----------------------------------------------------
extern "C" void kernel_launch(void* const* d_in, const int* in_sizes, int n_in,
                              void* d_out, int out_size)
{
    const float* x     = (const float*)d_in[0];
    const float* pre_h = (const float*)d_in[1];
    const float* Wf    = (const float*)d_in[2];
    const float* bf    = (const float*)d_in[3];
    const float* Wi    = (const float*)d_in[4];
    const float* bi    = (const float*)d_in[5];
    const float* Wh    = (const float*)d_in[6];
    const float* bh    = (const float*)d_in[7];
    float* out = (float*)d_out;

    cudaFuncSetAttribute(gemm_act, cudaFuncAttributeMaxDynamicSharedMemorySize, DYN_SMEM);

    prep<<<WBLKS + XBLKS, 256>>>(x, Wf, Wi, Wh);
    gemm_act<<<dim3(DIM / TILE_N, M_TOTAL / TILE_M), 256, DYN_SMEM>>>(bf, bi, bh);
    carry_scan<<<8, 256>>>(pre_h);
    chunk_apply<<<dim3(NCHUNK, BATCH, 4), 128>>>(out);
}

// round 16
// speedup vs baseline: 1.0905x; 1.0132x over previous
#include <cuda_runtime.h>
#include <cuda_fp16.h>

#define BATCH 4
#define SEQ   8192
#define DIM   512
#define M_TOTAL (BATCH*SEQ)   // 32768

#define NCHUNK 128
#define CHUNK  64

#define TILE_M 128
#define TILE_N 64
#define BK     32
#define NSTG   (DIM/BK)       // 16
#define STAGES 4

#define A_PITCH_B 80                     // bytes per A row (32 halfs + 8 pad)
#define A_BYTES   (TILE_M*A_PITCH_B)     // 10240
#define B_PITCH_B 144                    // bytes per B k-row (64 halfs + 8 pad)
#define B_GATE    (BK*B_PITCH_B)         // 4608
#define B_BYTES   (3*B_GATE)             // 13824
#define STG_BYTES (A_BYTES+B_BYTES)      // 24064
#define DYN_SMEM  (1024 + STAGES*STG_BYTES)

// ---------------- scratch ---------------------------------------------------
__device__ __half  g_x16[(size_t)M_TOTAL*DIM];   // x in fp16, 32MB
__device__ __half  g_w16[3*DIM*DIM];             // W fp16, [w][k][n], 1.5MB
__device__ __half2 g_fv[(size_t)M_TOTAL*DIM];    // (f,v) packed, 64MB
__device__ float   g_P[NCHUNK*BATCH*DIM];
__device__ float   g_V[NCHUNK*BATCH*DIM];
__device__ float   g_hin[NCHUNK*BATCH*DIM];

__device__ __forceinline__ float sigmoidf_(float x) { return 1.0f / (1.0f + __expf(-x)); }
__device__ __forceinline__ unsigned smem_u32(const void* p) {
    unsigned a;
    asm("{ .reg .u64 t; cvta.to.shared.u64 t, %1; cvt.u32.u64 %0, t; }" : "=r"(a) : "l"(p));
    return a;
}
__device__ __forceinline__ void cpasync16(unsigned dst, const void* src) {
    asm volatile("cp.async.cg.shared.global [%0], [%1], 16;" :: "r"(dst), "l"(src));
}
__device__ __forceinline__ void ldsm4(unsigned* r, unsigned addr) {
    asm volatile("ldmatrix.sync.aligned.m8n8.x4.shared.b16 {%0,%1,%2,%3}, [%4];"
                 : "=r"(r[0]), "=r"(r[1]), "=r"(r[2]), "=r"(r[3]) : "r"(addr));
}
__device__ __forceinline__ void ldsm4t(unsigned* r, unsigned addr) {
    asm volatile("ldmatrix.sync.aligned.m8n8.x4.trans.shared.b16 {%0,%1,%2,%3}, [%4];"
                 : "=r"(r[0]), "=r"(r[1]), "=r"(r[2]), "=r"(r[3]) : "r"(addr));
}
__device__ __forceinline__ void mma16816(float* c, const unsigned* a, unsigned b0, unsigned b1) {
    asm volatile("mma.sync.aligned.m16n8k16.row.col.f32.f16.f16.f32 "
                 "{%0,%1,%2,%3}, {%4,%5,%6,%7}, {%8,%9}, {%0,%1,%2,%3};"
                 : "+f"(c[0]), "+f"(c[1]), "+f"(c[2]), "+f"(c[3])
                 : "r"(a[0]), "r"(a[1]), "r"(a[2]), "r"(a[3]), "r"(b0), "r"(b1));
}

// ---------------- prep: x -> fp16 AND W -> fp16, 8 elems/thread -------------
#define WBLKS (3*DIM*DIM/2048)          // 384
#define XBLKS (M_TOTAL*DIM/2048)        // 8192

__global__ __launch_bounds__(256) void prep(
    const float* __restrict__ x,
    const float* __restrict__ Wf, const float* __restrict__ Wi,
    const float* __restrict__ Wh)
{
    if (blockIdx.x < WBLKS) {
        size_t j = ((size_t)blockIdx.x * 256 + threadIdx.x) * 8;
        int w = (int)(j >> 18);
        size_t off = j & (DIM*DIM - 1);
        const float* W = (w == 0) ? Wf : (w == 1) ? Wi : Wh;
        float4 t0 = *(const float4*)(W + off);
        float4 t1 = *(const float4*)(W + off + 4);
        __half2 h[4] = { __floats2half2_rn(t0.x, t0.y), __floats2half2_rn(t0.z, t0.w),
                         __floats2half2_rn(t1.x, t1.y), __floats2half2_rn(t1.z, t1.w) };
        *(float4*)(g_w16 + (size_t)w * DIM * DIM + off) = *(float4*)h;
    } else {
        size_t i = ((size_t)(blockIdx.x - WBLKS) * 256 + threadIdx.x) * 8;
        float4 t0 = *(const float4*)(x + i);
        float4 t1 = *(const float4*)(x + i + 4);
        __half2 h[4] = { __floats2half2_rn(t0.x, t0.y), __floats2half2_rn(t0.z, t0.w),
                         __floats2half2_rn(t1.x, t1.y), __floats2half2_rn(t1.z, t1.w) };
        *(float4*)(g_x16 + i) = *(float4*)h;
    }
}

// ---------------- fp16 mma.sync GEMM + activations + fused chunk reduce -----
// (R11 verbatim — measured)
__global__ __launch_bounds__(256) void gemm_act(
    const float* __restrict__ bfp, const float* __restrict__ bip,
    const float* __restrict__ bhp)
{
    extern __shared__ char dsm[];
    __shared__ float s_bias[3*TILE_N];

    const int tid  = threadIdx.x;
    const int wid  = tid >> 5;
    const int lane = tid & 31;
    const int wm   = wid >> 1;   // 0..3
    const int wn   = wid & 1;    // 0..1
    const int n0   = blockIdx.x * TILE_N;
    const int m0   = blockIdx.y * TILE_M;

    unsigned raw = smem_u32(dsm);
    unsigned sma = (raw + 1023u) & ~1023u;

    if (tid < 3*TILE_N) {
        int w = tid >> 6, c = tid & 63;
        const float* b = (w == 0) ? bfp : (w == 1) ? bip : bhp;
        s_bias[tid] = b[n0 + c];
    }

    float acc[3][2][4][4];
    #pragma unroll
    for (int g = 0; g < 3; g++)
        #pragma unroll
        for (int mi = 0; mi < 2; mi++)
            #pragma unroll
            for (int ni = 0; ni < 4; ni++)
                #pragma unroll
                for (int r = 0; r < 4; r++)
                    acc[g][mi][ni][r] = 0.0f;

    auto fill = [&](int buf, int k0e) {
        unsigned sb = sma + buf * STG_BYTES;
        #pragma unroll
        for (int i = 0; i < 2; i++) {          // A: 512 chunks
            int c = tid + 256 * i;
            int r = c >> 2, q = c & 3;
            cpasync16(sb + (unsigned)(r * A_PITCH_B + q * 16),
                      g_x16 + (size_t)(m0 + r) * DIM + k0e + q * 8);
        }
        #pragma unroll
        for (int i = 0; i < 3; i++) {          // B: 768 chunks
            int c = tid + 256 * i;
            int g = c >> 8, rq = c & 255;
            int k = rq >> 3, q = rq & 7;
            cpasync16(sb + (unsigned)(A_BYTES + g * B_GATE + k * B_PITCH_B + q * 16),
                      g_w16 + (size_t)g * DIM * DIM + (size_t)(k0e + k) * DIM + n0 + q * 8);
        }
        asm volatile("cp.async.commit_group;");
    };

    #pragma unroll
    for (int s = 0; s < STAGES - 1; s++) fill(s, s * BK);

    const int l15 = lane & 15;
    const int l16 = lane >> 4;

    for (int i = 0; i < NSTG; i++) {
        asm volatile("cp.async.wait_group %0;" :: "n"(STAGES - 2));
        __syncthreads();
        int j = i + STAGES - 1;
        if (j < NSTG) fill(j & (STAGES - 1), j * BK);
        else          asm volatile("cp.async.commit_group;");

        unsigned sb = sma + (i & (STAGES - 1)) * STG_BYTES;

        #pragma unroll
        for (int kh = 0; kh < 2; kh++) {
            int kk = kh * 16;
            unsigned a[2][4];
            #pragma unroll
            for (int mi = 0; mi < 2; mi++)
                ldsm4(a[mi], sb + (unsigned)((wm * 32 + mi * 16 + l15) * A_PITCH_B
                                              + (kk + l16 * 8) * 2));
            #pragma unroll
            for (int g = 0; g < 3; g++) {
                unsigned b[2][4];
                #pragma unroll
                for (int nh = 0; nh < 2; nh++)
                    ldsm4t(b[nh], sb + (unsigned)(A_BYTES + g * B_GATE
                                                  + (kk + l15) * B_PITCH_B
                                                  + (wn * 32 + nh * 16 + l16 * 8) * 2));
                #pragma unroll
                for (int ni = 0; ni < 4; ni++) {
                    unsigned b0 = b[ni >> 1][(ni & 1) * 2];
                    unsigned b1 = b[ni >> 1][(ni & 1) * 2 + 1];
                    #pragma unroll
                    for (int mi = 0; mi < 2; mi++)
                        mma16816(acc[g][mi][ni], a[mi], b0, b1);
                }
            }
        }
    }

    // ---- epilogue: activations -> smem staging (half2 f,v) ----
    __half2* sfv = (__half2*)(dsm + (sma - raw));
    const int PITCH = 65;   // half2 units per m-row

    #pragma unroll
    for (int mi = 0; mi < 2; mi++) {
        #pragma unroll
        for (int ni = 0; ni < 4; ni++) {
            int lm = wm * 32 + mi * 16 + (lane >> 2);
            int ln = wn * 32 + ni * 8 + 2 * (lane & 3);
            #pragma unroll
            for (int half = 0; half < 2; half++) {
                int m = lm + half * 8;
                #pragma unroll
                for (int e = 0; e < 2; e++) {
                    int c = ln + e;
                    float yf = acc[0][mi][ni][half * 2 + e] + s_bias[c];
                    float yi = acc[1][mi][ni][half * 2 + e] + s_bias[TILE_N + c];
                    float yh = acc[2][mi][ni][half * 2 + e] + s_bias[2*TILE_N + c];
                    float f  = sigmoidf_(yf);
                    float gg = (yh >= 0.0f) ? (yh + 0.5f) : sigmoidf_(yh);
                    float v  = sigmoidf_(yi) * gg;
                    sfv[m * PITCH + c] = __floats2half2_rn(f, v);
                }
            }
        }
    }
    __syncthreads();

    // ---- fused reduction: two 64-step chunks per tile ----
    {
        int c = tid >> 2;
        int q = tid & 3;          // segment: rows q*32 .. q*32+31
        float P = 1.0f, V = 0.0f;
        #pragma unroll 8
        for (int s = 0; s < 32; s++) {
            float2 fv = __half22float2(sfv[(q * 32 + s) * PITCH + c]);
            V = fmaf(fv.x, V, fv.y);
            P *= fv.x;
        }
        // combine segment pairs {0,1} and {2,3} -> one (P,V) per 64 steps
        float Po = __shfl_xor_sync(0xffffffff, P, 1);
        float Vo = __shfl_xor_sync(0xffffffff, V, 1);
        if ((q & 1) == 0) V = fmaf(Po, V, Vo);
        else              V = fmaf(P, Vo, V);
        P *= Po;
        if ((q & 1) == 0) {
            int bb = m0 / SEQ;
            int ck = (m0 % SEQ) / CHUNK + (q >> 1);
            size_t idx = (size_t)ck * (BATCH*DIM) + bb * DIM + n0 + c;
            g_P[idx] = P;
            g_V[idx] = V;
        }
    }

    // ---- store staging tile to global (coalesced) ----
    #pragma unroll 8
    for (int t = 0; t < 32; t++) {
        int idx = tid + 256 * t;
        int m = idx >> 6, c = idx & 63;
        g_fv[(size_t)(m0 + m) * DIM + n0 + c] = sfv[m * PITCH + c];
    }
}

// ---------------- carry scan over 128 chunks (2 batches of reg-preload) -----
__global__ void carry_scan(const float* __restrict__ pre_h)
{
    int ch = blockIdx.x * 256 + threadIdx.x;   // 0..2047
    float pv = pre_h[ch];
    float h = (pv >= 0.0f) ? (pv + 0.5f) : sigmoidf_(pv);
    #pragma unroll
    for (int half = 0; half < 2; half++) {
        float P[64], V[64];
        #pragma unroll
        for (int c = 0; c < 64; c++)
            P[c] = g_P[(size_t)(half * 64 + c) * (BATCH*DIM) + ch];
        #pragma unroll
        for (int c = 0; c < 64; c++)
            V[c] = g_V[(size_t)(half * 64 + c) * (BATCH*DIM) + ch];
        #pragma unroll
        for (int c = 0; c < 64; c++) {
            g_hin[(size_t)(half * 64 + c) * (BATCH*DIM) + ch] = h;
            h = fmaf(P[c], h, V[c]);
        }
    }
}

// ---------------- apply: 1024 blocks x 256thr (measured optimum 19.2us) -----
__global__ __launch_bounds__(256) void chunk_apply(float* __restrict__ out)
{
    int ck = blockIdx.x;
    int b  = blockIdx.y;
    int n  = blockIdx.z * 256 + threadIdx.x;
    float h = g_hin[(size_t)ck * (BATCH*DIM) + b * DIM + n];
    size_t base = ((size_t)(b * SEQ + ck * CHUNK)) * DIM + n;
    #pragma unroll 8
    for (int t = 0; t < CHUNK; t++) {
        float2 fv = __half22float2(g_fv[base + (size_t)t * DIM]);
        h = fmaf(fv.x, h, fv.y);
        out[base + (size_t)t * DIM] = h;
    }
}

// ---------------- launch ----------------------------------------------------
extern "C" void kernel_launch(void* const* d_in, const int* in_sizes, int n_in,
                              void* d_out, int out_size)
{
    const float* x     = (const float*)d_in[0];
    const float* pre_h = (const float*)d_in[1];
    const float* Wf    = (const float*)d_in[2];
    const float* bf    = (const float*)d_in[3];
    const float* Wi    = (const float*)d_in[4];
    const float* bi    = (const float*)d_in[5];
    const float* Wh    = (const float*)d_in[6];
    const float* bh    = (const float*)d_in[7];
    float* out = (float*)d_out;

    cudaFuncSetAttribute(gemm_act, cudaFuncAttributeMaxDynamicSharedMemorySize, DYN_SMEM);

    prep<<<WBLKS + XBLKS, 256>>>(x, Wf, Wi, Wh);
    gemm_act<<<dim3(DIM / TILE_N, M_TOTAL / TILE_M), 256, DYN_SMEM>>>(bf, bi, bh);
    carry_scan<<<8, 256>>>(pre_h);
    chunk_apply<<<dim3(NCHUNK, BATCH, 2), 256>>>(out);
}